// round 1
// baseline (speedup 1.0000x reference)
#include <cuda_runtime.h>
#include <math.h>

#define NLAT 64
#define NLON 128
#define GPTS 8192   // NLAT*NLON
#define NS   1024   // stations
#define HD   256    // hidden dim
#define NB   2      // batch

// Normalized softmax weights, layout [b][g][s] so GEMM k-dim (s) is contiguous.
__device__ float g_P[(size_t)NB * GPTS * NS];

// ---------------------------------------------------------------------------
// Phase 1: per (b,g) compute 1024 station logits via the tiny MLP, softmax
// over stations, write normalized weights to g_P.
// One block per (b,g); 256 threads; 4 stations per thread.
// ---------------------------------------------------------------------------
__global__ __launch_bounds__(256) void weights_kernel(
    const float* __restrict__ coords,   // [B, S, 3]
    const float* __restrict__ mask,     // [B, S]
    const float* __restrict__ W1,       // [3, 32]
    const float* __restrict__ b1,       // [32]
    const float* __restrict__ W2,       // [32, 1]
    const float* __restrict__ b2)       // [1]
{
    __shared__ float sW1[96];
    __shared__ float sb1[32];
    __shared__ float sW2[32];
    __shared__ float sb2;
    __shared__ float red[8];

    const int tid = threadIdx.x;
    if (tid < 96) sW1[tid] = W1[tid];
    if (tid < 32) { sb1[tid] = b1[tid]; sW2[tid] = W2[tid]; }
    if (tid == 0) sb2 = b2[0];
    __syncthreads();

    const int g = blockIdx.x;
    const int b = blockIdx.y;

    const float glat = -90.0f  + (float)(g >> 7)   * (180.0f / 63.0f);
    const float glon = -180.0f + (float)(g & 127)  * (360.0f / 127.0f);

    float logit[4];
#pragma unroll
    for (int k = 0; k < 4; k++) {
        const int s = tid + 256 * k;
        const float* c = coords + ((size_t)b * NS + s) * 3;
        const float slat = c[0];
        const float slon = c[1];
        const float dlat = slat - glat;
        const float dlon = slon - glon;
        const float dist = sqrtf(fmaf(dlat, dlat, fmaf(dlon, dlon, 1e-6f)));

        float acc = sb2;
#pragma unroll
        for (int j = 0; j < 32; j++) {
            float z = fmaf(dist, sW1[j],
                      fmaf(dlat, sW1[32 + j],
                      fmaf(dlon, sW1[64 + j], sb1[j])));
            // exact GELU: z * Phi(z)
            float h = z * normcdff(z);
            acc = fmaf(h, sW2[j], acc);
        }
        // softplus, numerically stable
        float sp = fmaxf(acc, 0.0f) + log1pf(expf(-fabsf(acc)));
        logit[k] = sp * mask[b * NS + s];
    }

    // ---- block max reduction ----
    float m = fmaxf(fmaxf(logit[0], logit[1]), fmaxf(logit[2], logit[3]));
#pragma unroll
    for (int off = 16; off > 0; off >>= 1)
        m = fmaxf(m, __shfl_xor_sync(0xffffffffu, m, off));
    if ((tid & 31) == 0) red[tid >> 5] = m;
    __syncthreads();
    {
        float t = red[tid & 7];
#pragma unroll
        for (int off = 4; off > 0; off >>= 1)
            t = fmaxf(t, __shfl_xor_sync(0xffffffffu, t, off));
        m = __shfl_sync(0xffffffffu, t, 0);
    }
    __syncthreads();

    // ---- exp and block sum reduction ----
    float e[4];
    float sum = 0.0f;
#pragma unroll
    for (int k = 0; k < 4; k++) {
        e[k] = expf(logit[k] - m);
        sum += e[k];
    }
#pragma unroll
    for (int off = 16; off > 0; off >>= 1)
        sum += __shfl_xor_sync(0xffffffffu, sum, off);
    if ((tid & 31) == 0) red[tid >> 5] = sum;
    __syncthreads();
    {
        float t = red[tid & 7];
#pragma unroll
        for (int off = 4; off > 0; off >>= 1)
            t += __shfl_xor_sync(0xffffffffu, t, off);
        sum = __shfl_sync(0xffffffffu, t, 0);
    }

    const float inv = 1.0f / sum;
    float* Prow = g_P + ((size_t)b * GPTS + g) * NS;
#pragma unroll
    for (int k = 0; k < 4; k++)
        Prow[tid + 256 * k] = e[k] * inv;
}

// ---------------------------------------------------------------------------
// Phase 2: per batch, C[g,d] = sum_s P[g,s] * F[s,d]; write out[b,d,g].
// 128x128 tile, BS=32 k-chunk, 256 threads, 8x8 microtile.
// ---------------------------------------------------------------------------
#define BG 128
#define BD 128
#define BS 32

__global__ __launch_bounds__(256) void grid_gemm_kernel(
    const float* __restrict__ F,   // [B, S, D]
    float* __restrict__ out)       // [B, D, G]
{
    __shared__ float As[BS][BG + 1];  // [s][g], +1 pad for conflict-free transpose store
    __shared__ float Bs[BS][BD];      // [s][d]

    const int tid = threadIdx.x;
    const int g0 = blockIdx.x * BG;
    const int d0 = blockIdx.y * BD;
    const int b  = blockIdx.z;

    const float* P  = g_P + (size_t)b * GPTS * NS;
    const float* Fb = F   + (size_t)b * NS * HD;

    const int tx = tid & 15;   // g-fragment selector: g = g0 + tx + 16*i
    const int ty = tid >> 4;   // d-fragment selector: d = d0 + ty*8 + j

    float acc[8][8];
#pragma unroll
    for (int i = 0; i < 8; i++)
#pragma unroll
        for (int j = 0; j < 8; j++) acc[i][j] = 0.0f;

    for (int sc = 0; sc < NS; sc += BS) {
        // Load P tile [BG rows of g][BS cols of s], transpose into As[s][g].
#pragma unroll
        for (int q = 0; q < 4; q++) {
            int slot = tid + 256 * q;        // 1024 float4 slots
            int gl = slot >> 3;              // 0..127
            int sl = (slot & 7) * 4;         // 0..28
            float4 v = *(const float4*)(P + (size_t)(g0 + gl) * NS + sc + sl);
            As[sl + 0][gl] = v.x;
            As[sl + 1][gl] = v.y;
            As[sl + 2][gl] = v.z;
            As[sl + 3][gl] = v.w;
        }
        // Load F tile [BS rows of s][BD cols of d] directly.
#pragma unroll
        for (int q = 0; q < 4; q++) {
            int slot = tid + 256 * q;        // 1024 float4 slots
            int sl = slot >> 5;              // 0..31
            int dl = (slot & 31) * 4;        // 0..124
            *(float4*)(&Bs[sl][dl]) =
                *(const float4*)(Fb + (size_t)(sc + sl) * HD + d0 + dl);
        }
        __syncthreads();

#pragma unroll
        for (int ss = 0; ss < BS; ss++) {
            float a[8], bb[8];
#pragma unroll
            for (int i = 0; i < 8; i++) a[i] = As[ss][tx + 16 * i];
#pragma unroll
            for (int j = 0; j < 8; j++) bb[j] = Bs[ss][ty * 8 + j];
#pragma unroll
            for (int i = 0; i < 8; i++)
#pragma unroll
                for (int j = 0; j < 8; j++)
                    acc[i][j] = fmaf(a[i], bb[j], acc[i][j]);
        }
        __syncthreads();
    }

    // Epilogue: out[b, d, g]
    float* ob = out + (size_t)b * HD * GPTS;
#pragma unroll
    for (int j = 0; j < 8; j++) {
        const int d = d0 + ty * 8 + j;
        float* orow = ob + (size_t)d * GPTS + g0 + tx;
#pragma unroll
        for (int i = 0; i < 8; i++)
            orow[16 * i] = acc[i][j];
    }
}

// ---------------------------------------------------------------------------
// kernel_launch
// Inputs (metadata order): station_features, station_coords, mask, W1, b1, W2, b2
// ---------------------------------------------------------------------------
extern "C" void kernel_launch(void* const* d_in, const int* in_sizes, int n_in,
                              void* d_out, int out_size)
{
    const float* features = (const float*)d_in[0];  // [2,1024,256]
    const float* coords   = (const float*)d_in[1];  // [2,1024,3]
    const float* mask     = (const float*)d_in[2];  // [2,1024]
    const float* W1       = (const float*)d_in[3];  // [3,32]
    const float* b1       = (const float*)d_in[4];  // [32]
    const float* W2       = (const float*)d_in[5];  // [32,1]
    const float* b2       = (const float*)d_in[6];  // [1]
    float* out            = (float*)d_out;          // [2,256,64,128]

    dim3 grid1(GPTS, NB);
    weights_kernel<<<grid1, 256>>>(coords, mask, W1, b1, W2, b2);

    dim3 grid2(GPTS / BG, HD / BD, NB);
    grid_gemm_kernel<<<grid2, 256>>>(features, out);
}

// round 2
// speedup vs baseline: 2.7933x; 2.7933x over previous
#include <cuda_runtime.h>
#include <math.h>
#include <float.h>

#define NLAT 64
#define NLON 128
#define GPTS 8192   // NLAT*NLON
#define NS   1024   // stations
#define HD   256    // hidden dim
#define NB   2      // batch

#define SAT_THR 5.0f

// Normalized softmax weights, layout [b][s][g] (g contiguous).
__device__ float g_P[(size_t)NB * NS * GPTS];

// ---------------------------------------------------------------------------
// A&S 7.1.26 erfc-based GELU for the non-saturated path.
// ---------------------------------------------------------------------------
__device__ __forceinline__ float gelu_slow(float z)
{
    const float x  = fabsf(z) * 0.70710678118654752f;
    const float t  = __fdividef(1.0f, fmaf(0.3275911f, x, 1.0f));
    float p = fmaf(t, 1.061405429f, -1.453152027f);
    p = fmaf(t, p, 1.421413741f);
    p = fmaf(t, p, -0.284496736f);
    p = fmaf(t, p, 0.254829592f);
    p = p * t;
    const float e = __expf(-x * x);
    const float erfc_abs = p * e;                       // erfc(x), x>=0
    const float phi = (z >= 0.0f) ? fmaf(-0.5f, erfc_abs, 1.0f)
                                  : 0.5f * erfc_abs;
    return z * phi;
}

// ---------------------------------------------------------------------------
// Phase 1: logits + fused softmax.
// Grid (GPTS/32, NB), 256 threads = 8 warps.
// lane -> g = blockIdx.x*32 + lane (32 consecutive lon points)
// warp -> s-chunk of 128 stations
// ---------------------------------------------------------------------------
__global__ __launch_bounds__(256) void weights_kernel(
    const float* __restrict__ coords,   // [B, S, 3]
    const float* __restrict__ mask,     // [B, S]
    const float* __restrict__ W1,       // [3, 32]
    const float* __restrict__ b1,       // [32]
    const float* __restrict__ W2,       // [32, 1]
    const float* __restrict__ b2)       // [1]
{
    __shared__ __align__(16) float sW0[32];   // W1 row 0 (dist)
    __shared__ __align__(16) float sWa[32];   // W1 row 1 (dlat)
    __shared__ __align__(16) float sWo[32];   // W1 row 2 (dlon)
    __shared__ __align__(16) float sB1[32];
    __shared__ __align__(16) float sW2[32];
    __shared__ float sb2s;
    __shared__ float red_m[8][32];
    __shared__ float red_s[8][32];

    const int tid  = threadIdx.x;
    const int lane = tid & 31;
    const int wrp  = tid >> 5;

    if (tid < 32)            sW0[tid]       = W1[tid];
    else if (tid < 64)       sWa[tid - 32]  = W1[tid];
    else if (tid < 96)       sWo[tid - 64]  = W1[tid];
    else if (tid < 128)      sB1[tid - 96]  = b1[tid - 96];
    else if (tid < 160)      sW2[tid - 128] = W2[tid - 128];
    if (tid == 0)            sb2s = b2[0];
    __syncthreads();

    const int g = blockIdx.x * 32 + lane;
    const int b = blockIdx.y;

    const float glat = -90.0f  + (float)(g >> 7)  * (180.0f / 63.0f);
    const float glon = -180.0f + (float)(g & 127) * (360.0f / 127.0f);

    const float b2v = sb2s;
    float* Pb = g_P + (size_t)b * NS * GPTS;

    float m_run = -FLT_MAX;
    float s_run = 0.0f;

    const int s_base = wrp * 128;

#pragma unroll 1
    for (int it = 0; it < 128; it++) {
        const int s = s_base + it;
        const float slat = coords[((size_t)b * NS + s) * 3 + 0];
        const float slon = coords[((size_t)b * NS + s) * 3 + 1];
        const float dlat = slat - glat;
        const float dlon = slon - glon;
        const float dist = sqrtf(fmaf(dlat, dlat, fmaf(dlon, dlon, 1e-6f)));

        float z[32];
        float zmin = FLT_MAX;
#pragma unroll
        for (int q = 0; q < 8; q++) {
            const float4 w0 = *(const float4*)&sW0[4 * q];
            const float4 wa = *(const float4*)&sWa[4 * q];
            const float4 wo = *(const float4*)&sWo[4 * q];
            const float4 bb = *(const float4*)&sB1[4 * q];
            z[4*q+0] = fmaf(dist, w0.x, fmaf(dlat, wa.x, fmaf(dlon, wo.x, bb.x)));
            z[4*q+1] = fmaf(dist, w0.y, fmaf(dlat, wa.y, fmaf(dlon, wo.y, bb.y)));
            z[4*q+2] = fmaf(dist, w0.z, fmaf(dlat, wa.z, fmaf(dlon, wo.z, bb.z)));
            z[4*q+3] = fmaf(dist, w0.w, fmaf(dlat, wa.w, fmaf(dlon, wo.w, bb.w)));
            zmin = fminf(zmin, fminf(fminf(fabsf(z[4*q+0]), fabsf(z[4*q+1])),
                                     fminf(fabsf(z[4*q+2]), fabsf(z[4*q+3]))));
        }

        float acc = b2v;
        if (__all_sync(0xffffffffu, zmin > SAT_THR)) {
            // all 32 hidden units saturated for the whole warp
#pragma unroll
            for (int q = 0; q < 8; q++) {
                const float4 w2 = *(const float4*)&sW2[4 * q];
                acc = fmaf(fmaxf(z[4*q+0], 0.0f), w2.x, acc);
                acc = fmaf(fmaxf(z[4*q+1], 0.0f), w2.y, acc);
                acc = fmaf(fmaxf(z[4*q+2], 0.0f), w2.z, acc);
                acc = fmaf(fmaxf(z[4*q+3], 0.0f), w2.w, acc);
            }
        } else {
#pragma unroll
            for (int q = 0; q < 8; q++) {
                const float4 w2 = *(const float4*)&sW2[4 * q];
                acc = fmaf(gelu_slow(z[4*q+0]), w2.x, acc);
                acc = fmaf(gelu_slow(z[4*q+1]), w2.y, acc);
                acc = fmaf(gelu_slow(z[4*q+2]), w2.z, acc);
                acc = fmaf(gelu_slow(z[4*q+3]), w2.w, acc);
            }
        }

        // softplus * mask
        const float sp = fmaxf(acc, 0.0f) + log1pf(__expf(-fabsf(acc)));
        const float l  = sp * mask[(size_t)b * NS + s];

        // online softmax accumulation
        const float mnew = fmaxf(m_run, l);
        s_run = fmaf(s_run, __expf(m_run - mnew), __expf(l - mnew));
        m_run = mnew;

        // stash raw logit
        Pb[(size_t)s * GPTS + g] = l;
    }

    // cross-warp combine (per lane == per g)
    red_m[wrp][lane] = m_run;
    red_s[wrp][lane] = s_run;
    __syncthreads();

    float M = -FLT_MAX;
#pragma unroll
    for (int w = 0; w < 8; w++) M = fmaxf(M, red_m[w][lane]);
    float Stot = 0.0f;
#pragma unroll
    for (int w = 0; w < 8; w++) Stot += red_s[w][lane] * __expf(red_m[w][lane] - M);

    const float inv = 1.0f / Stot;

    // normalize in place
#pragma unroll 1
    for (int it = 0; it < 128; it++) {
        const int s = s_base + it;
        const float l = Pb[(size_t)s * GPTS + g];
        Pb[(size_t)s * GPTS + g] = __expf(l - M) * inv;
    }
}

// ---------------------------------------------------------------------------
// Phase 2: C[g,d] = sum_s P[s,g] * F[s,d]; write out[b,d,g].
// 128x128 tile, BS=16 k-chunk, double-buffered smem, 256 threads, 8x8 microtile.
// ---------------------------------------------------------------------------
#define BSK 16

__global__ __launch_bounds__(256) void grid_gemm_kernel(
    const float* __restrict__ F,   // [B, S, D]
    float* __restrict__ out)       // [B, D, G]
{
    __shared__ float As[2][BSK][128];   // [s][g]
    __shared__ float Bs[2][BSK][128];   // [s][d]

    const int tid = threadIdx.x;
    const int tx  = tid & 15;
    const int ty  = tid >> 4;
    const int g0  = blockIdx.x * 128;
    const int d0  = blockIdx.y * 128;
    const int b   = blockIdx.z;

    const float* P  = g_P + (size_t)b * NS * GPTS;
    const float* Fb = F   + (size_t)b * NS * HD;

    // loader indexing: 512 float4 slots per tile, 2 per thread
    const int aslot0 = tid;            // sl = slot>>5, gv = slot&31
    const int aslot1 = tid + 256;

    float4 ra[2], rb[2];

    // preload chunk 0
    {
        const int sl0 = aslot0 >> 5, v0 = (aslot0 & 31) * 4;
        const int sl1 = aslot1 >> 5, v1 = (aslot1 & 31) * 4;
        ra[0] = *(const float4*)(P  + (size_t)sl0 * GPTS + g0 + v0);
        ra[1] = *(const float4*)(P  + (size_t)sl1 * GPTS + g0 + v1);
        rb[0] = *(const float4*)(Fb + (size_t)sl0 * HD   + d0 + v0);
        rb[1] = *(const float4*)(Fb + (size_t)sl1 * HD   + d0 + v1);
        *(float4*)&As[0][sl0][v0] = ra[0];
        *(float4*)&As[0][sl1][v1] = ra[1];
        *(float4*)&Bs[0][sl0][v0] = rb[0];
        *(float4*)&Bs[0][sl1][v1] = rb[1];
    }
    __syncthreads();

    float acc[8][8];
#pragma unroll
    for (int i = 0; i < 8; i++)
#pragma unroll
        for (int j = 0; j < 8; j++) acc[i][j] = 0.0f;

    const int NC = NS / BSK;   // 64
#pragma unroll 1
    for (int c = 0; c < NC; c++) {
        const int cur = c & 1;

        if (c + 1 < NC) {
            const int sc = (c + 1) * BSK;
            const int sl0 = aslot0 >> 5, v0 = (aslot0 & 31) * 4;
            const int sl1 = aslot1 >> 5, v1 = (aslot1 & 31) * 4;
            ra[0] = *(const float4*)(P  + (size_t)(sc + sl0) * GPTS + g0 + v0);
            ra[1] = *(const float4*)(P  + (size_t)(sc + sl1) * GPTS + g0 + v1);
            rb[0] = *(const float4*)(Fb + (size_t)(sc + sl0) * HD   + d0 + v0);
            rb[1] = *(const float4*)(Fb + (size_t)(sc + sl1) * HD   + d0 + v1);
        }

#pragma unroll
        for (int ss = 0; ss < BSK; ss++) {
            const float4 a0 = *(const float4*)&As[cur][ss][tx * 4];
            const float4 a1 = *(const float4*)&As[cur][ss][64 + tx * 4];
            const float4 b0 = *(const float4*)&Bs[cur][ss][ty * 4];
            const float4 b1 = *(const float4*)&Bs[cur][ss][64 + ty * 4];
            const float av[8] = {a0.x, a0.y, a0.z, a0.w, a1.x, a1.y, a1.z, a1.w};
            const float bv[8] = {b0.x, b0.y, b0.z, b0.w, b1.x, b1.y, b1.z, b1.w};
#pragma unroll
            for (int i = 0; i < 8; i++)
#pragma unroll
                for (int j = 0; j < 8; j++)
                    acc[i][j] = fmaf(av[i], bv[j], acc[i][j]);
        }

        if (c + 1 < NC) {
            const int nxt = cur ^ 1;
            const int sl0 = aslot0 >> 5, v0 = (aslot0 & 31) * 4;
            const int sl1 = aslot1 >> 5, v1 = (aslot1 & 31) * 4;
            *(float4*)&As[nxt][sl0][v0] = ra[0];
            *(float4*)&As[nxt][sl1][v1] = ra[1];
            *(float4*)&Bs[nxt][sl0][v0] = rb[0];
            *(float4*)&Bs[nxt][sl1][v1] = rb[1];
            __syncthreads();
        }
    }

    // Epilogue: out[b, d, g]; d = d0 + (j<4 ? ty*4+j : 64+ty*4+j-4)
    float* ob = out + (size_t)b * HD * GPTS;
#pragma unroll
    for (int j = 0; j < 8; j++) {
        const int d = d0 + ((j < 4) ? (ty * 4 + j) : (64 + ty * 4 + j - 4));
        float* orow = ob + (size_t)d * GPTS + g0;
        float4 lo = make_float4(acc[0][j], acc[1][j], acc[2][j], acc[3][j]);
        float4 hi = make_float4(acc[4][j], acc[5][j], acc[6][j], acc[7][j]);
        *(float4*)(orow + tx * 4)      = lo;
        *(float4*)(orow + 64 + tx * 4) = hi;
    }
}

// ---------------------------------------------------------------------------
// kernel_launch
// Inputs: station_features, station_coords, mask, W1, b1, W2, b2
// ---------------------------------------------------------------------------
extern "C" void kernel_launch(void* const* d_in, const int* in_sizes, int n_in,
                              void* d_out, int out_size)
{
    const float* features = (const float*)d_in[0];  // [2,1024,256]
    const float* coords   = (const float*)d_in[1];  // [2,1024,3]
    const float* mask     = (const float*)d_in[2];  // [2,1024]
    const float* W1       = (const float*)d_in[3];  // [3,32]
    const float* b1       = (const float*)d_in[4];  // [32]
    const float* W2       = (const float*)d_in[5];  // [32,1]
    const float* b2       = (const float*)d_in[6];  // [1]
    float* out            = (float*)d_out;          // [2,256,64,128]

    dim3 grid1(GPTS / 32, NB);
    weights_kernel<<<grid1, 256>>>(coords, mask, W1, b1, W2, b2);

    dim3 grid2(GPTS / 128, HD / 128, NB);
    grid_gemm_kernel<<<grid2, 256>>>(features, out);
}

// round 3
// speedup vs baseline: 5.0956x; 1.8242x over previous
#include <cuda_runtime.h>
#include <math.h>
#include <float.h>

#define NLAT 64
#define NLON 128
#define GPTS 8192   // NLAT*NLON
#define NS   1024   // stations
#define HD   256    // hidden dim
#define NB   2      // batch

// Normalized softmax weights, layout [b][s][g] (g contiguous).
__device__ float g_P[(size_t)NB * NS * GPTS];

// ---------------------------------------------------------------------------
// tanh-form GELU using the hardware MUFU.TANH. Branch-free, saturates exactly.
// ---------------------------------------------------------------------------
__device__ __forceinline__ float gelu_tanh(float z)
{
    const float z2 = z * z;
    const float u  = z * fmaf(z2, 0.0356774081f, 0.7978845608f);
    float t;
    asm("tanh.approx.f32 %0, %1;" : "=f"(t) : "f"(u));
    return z * fmaf(t, 0.5f, 0.5f);
}

// ---------------------------------------------------------------------------
// Phase 1: logits + fused online softmax.
// Grid (GPTS/32, NB), 256 threads = 8 warps.
// lane -> g = blockIdx.x*32 + lane; warp -> 128-station chunk.
// ---------------------------------------------------------------------------
__global__ __launch_bounds__(256) void weights_kernel(
    const float* __restrict__ coords,   // [B, S, 3]
    const float* __restrict__ mask,     // [B, S]
    const float* __restrict__ W1,       // [3, 32]
    const float* __restrict__ b1,       // [32]
    const float* __restrict__ W2,       // [32, 1]
    const float* __restrict__ b2)       // [1]
{
    __shared__ __align__(16) float sW0[32];   // W1 row 0 (dist)
    __shared__ __align__(16) float sWa[32];   // W1 row 1 (dlat)
    __shared__ __align__(16) float sWo[32];   // W1 row 2 (dlon)
    __shared__ __align__(16) float sB1[32];
    __shared__ __align__(16) float sW2[32];
    __shared__ float sLat[NS];
    __shared__ float sLon[NS];
    __shared__ float sMask[NS];
    __shared__ float sb2s;
    __shared__ float red_m[8][32];
    __shared__ float red_s[8][32];

    const int tid  = threadIdx.x;
    const int lane = tid & 31;
    const int wrp  = tid >> 5;
    const int b    = blockIdx.y;

    if (tid < 32) {
        sW0[tid] = W1[tid];
        sWa[tid] = W1[32 + tid];
        sWo[tid] = W1[64 + tid];
        sB1[tid] = b1[tid];
        sW2[tid] = W2[tid];
    }
    if (tid == 0) sb2s = b2[0];

    for (int s = tid; s < NS; s += 256) {
        sLat[s]  = coords[((size_t)b * NS + s) * 3 + 0];
        sLon[s]  = coords[((size_t)b * NS + s) * 3 + 1];
        sMask[s] = mask[(size_t)b * NS + s];
    }
    __syncthreads();

    const int g = blockIdx.x * 32 + lane;
    const float glat = -90.0f  + (float)(g >> 7)  * (180.0f / 63.0f);
    const float glon = -180.0f + (float)(g & 127) * (360.0f / 127.0f);

    const float b2v = sb2s;
    float* Pb = g_P + (size_t)b * NS * GPTS;

    float m_run = -FLT_MAX;
    float s_run = 0.0f;
    const int s_base = wrp * 128;

#pragma unroll 1
    for (int it = 0; it < 128; it += 2) {
        const int s0 = s_base + it;
        const int s1 = s0 + 1;

        const float dlat0 = sLat[s0] - glat;
        const float dlon0 = sLon[s0] - glon;
        const float dist0 = sqrtf(fmaf(dlat0, dlat0, fmaf(dlon0, dlon0, 1e-6f)));
        const float dlat1 = sLat[s1] - glat;
        const float dlon1 = sLon[s1] - glon;
        const float dist1 = sqrtf(fmaf(dlat1, dlat1, fmaf(dlon1, dlon1, 1e-6f)));

        float acc0 = b2v;
        float acc1 = b2v;

#pragma unroll
        for (int q = 0; q < 8; q++) {
            const float4 w0 = *(const float4*)&sW0[4 * q];
            const float4 wa = *(const float4*)&sWa[4 * q];
            const float4 wo = *(const float4*)&sWo[4 * q];
            const float4 bb = *(const float4*)&sB1[4 * q];
            const float4 w2 = *(const float4*)&sW2[4 * q];

            float z;
            z = fmaf(dist0, w0.x, fmaf(dlat0, wa.x, fmaf(dlon0, wo.x, bb.x)));
            acc0 = fmaf(gelu_tanh(z), w2.x, acc0);
            z = fmaf(dist0, w0.y, fmaf(dlat0, wa.y, fmaf(dlon0, wo.y, bb.y)));
            acc0 = fmaf(gelu_tanh(z), w2.y, acc0);
            z = fmaf(dist0, w0.z, fmaf(dlat0, wa.z, fmaf(dlon0, wo.z, bb.z)));
            acc0 = fmaf(gelu_tanh(z), w2.z, acc0);
            z = fmaf(dist0, w0.w, fmaf(dlat0, wa.w, fmaf(dlon0, wo.w, bb.w)));
            acc0 = fmaf(gelu_tanh(z), w2.w, acc0);

            z = fmaf(dist1, w0.x, fmaf(dlat1, wa.x, fmaf(dlon1, wo.x, bb.x)));
            acc1 = fmaf(gelu_tanh(z), w2.x, acc1);
            z = fmaf(dist1, w0.y, fmaf(dlat1, wa.y, fmaf(dlon1, wo.y, bb.y)));
            acc1 = fmaf(gelu_tanh(z), w2.y, acc1);
            z = fmaf(dist1, w0.z, fmaf(dlat1, wa.z, fmaf(dlon1, wo.z, bb.z)));
            acc1 = fmaf(gelu_tanh(z), w2.z, acc1);
            z = fmaf(dist1, w0.w, fmaf(dlat1, wa.w, fmaf(dlon1, wo.w, bb.w)));
            acc1 = fmaf(gelu_tanh(z), w2.w, acc1);
        }

        // softplus * mask
        const float sp0 = fmaxf(acc0, 0.0f) + __logf(1.0f + __expf(-fabsf(acc0)));
        const float sp1 = fmaxf(acc1, 0.0f) + __logf(1.0f + __expf(-fabsf(acc1)));
        const float l0  = sp0 * sMask[s0];
        const float l1  = sp1 * sMask[s1];

        // online softmax accumulation
        const float mnew = fmaxf(m_run, fmaxf(l0, l1));
        s_run = fmaf(s_run, __expf(m_run - mnew),
                     __expf(l0 - mnew) + __expf(l1 - mnew));
        m_run = mnew;

        Pb[(size_t)s0 * GPTS + g] = l0;
        Pb[(size_t)s1 * GPTS + g] = l1;
    }

    // cross-warp combine (per lane == per g)
    red_m[wrp][lane] = m_run;
    red_s[wrp][lane] = s_run;
    __syncthreads();

    float M = -FLT_MAX;
#pragma unroll
    for (int w = 0; w < 8; w++) M = fmaxf(M, red_m[w][lane]);
    float Stot = 0.0f;
#pragma unroll
    for (int w = 0; w < 8; w++) Stot += red_s[w][lane] * __expf(red_m[w][lane] - M);

    const float inv = 1.0f / Stot;

    // normalize in place
#pragma unroll 1
    for (int it = 0; it < 128; it++) {
        const int s = s_base + it;
        const float l = Pb[(size_t)s * GPTS + g];
        Pb[(size_t)s * GPTS + g] = __expf(l - M) * inv;
    }
}

// ---------------------------------------------------------------------------
// Phase 2: C[g,d] = sum_s P[s,g] * F[s,d]; write out[b,d,g].
// 128(g) x 64(d) tile, BSK=16, double-buffered, 256 threads, 8x4 microtile.
// ---------------------------------------------------------------------------
#define TG  128
#define TD  64
#define BSK 16

__global__ __launch_bounds__(256) void grid_gemm_kernel(
    const float* __restrict__ F,   // [B, S, D]
    float* __restrict__ out)       // [B, D, G]
{
    __shared__ float As[2][BSK][TG];   // [s][g]
    __shared__ float Bs[2][BSK][TD];   // [s][d]

    const int tid = threadIdx.x;
    const int tx  = tid & 15;          // g fragment
    const int ty  = tid >> 4;          // d fragment (0..15)
    const int g0  = blockIdx.x * TG;
    const int d0  = blockIdx.y * TD;
    const int b   = blockIdx.z;

    const float* P  = g_P + (size_t)b * NS * GPTS;
    const float* Fb = F   + (size_t)b * NS * HD;

    // loader indexing
    const int a_sl0 = tid >> 5;            // rows 0..7
    const int a_sl1 = a_sl0 + 8;           // rows 8..15
    const int a_gv  = (tid & 31) * 4;
    const int b_sl  = tid >> 4;            // rows 0..15
    const int b_dv  = (tid & 15) * 4;

    float4 ra0, ra1, rbv;

    // preload chunk 0
    ra0 = *(const float4*)(P  + (size_t)a_sl0 * GPTS + g0 + a_gv);
    ra1 = *(const float4*)(P  + (size_t)a_sl1 * GPTS + g0 + a_gv);
    rbv = *(const float4*)(Fb + (size_t)b_sl  * HD   + d0 + b_dv);
    *(float4*)&As[0][a_sl0][a_gv] = ra0;
    *(float4*)&As[0][a_sl1][a_gv] = ra1;
    *(float4*)&Bs[0][b_sl][b_dv]  = rbv;
    __syncthreads();

    float acc[8][4];
#pragma unroll
    for (int i = 0; i < 8; i++)
#pragma unroll
        for (int j = 0; j < 4; j++) acc[i][j] = 0.0f;

    const int NC = NS / BSK;   // 64
#pragma unroll 1
    for (int c = 0; c < NC; c++) {
        const int cur = c & 1;

        if (c + 1 < NC) {
            const int sc = (c + 1) * BSK;
            ra0 = *(const float4*)(P  + (size_t)(sc + a_sl0) * GPTS + g0 + a_gv);
            ra1 = *(const float4*)(P  + (size_t)(sc + a_sl1) * GPTS + g0 + a_gv);
            rbv = *(const float4*)(Fb + (size_t)(sc + b_sl)  * HD   + d0 + b_dv);
        }

#pragma unroll
        for (int ss = 0; ss < BSK; ss++) {
            const float4 a0 = *(const float4*)&As[cur][ss][tx * 4];
            const float4 a1 = *(const float4*)&As[cur][ss][64 + tx * 4];
            const float4 bb = *(const float4*)&Bs[cur][ss][ty * 4];
            const float av[8] = {a0.x, a0.y, a0.z, a0.w, a1.x, a1.y, a1.z, a1.w};
            const float bv[4] = {bb.x, bb.y, bb.z, bb.w};
#pragma unroll
            for (int i = 0; i < 8; i++)
#pragma unroll
                for (int j = 0; j < 4; j++)
                    acc[i][j] = fmaf(av[i], bv[j], acc[i][j]);
        }

        if (c + 1 < NC) {
            const int nxt = cur ^ 1;
            *(float4*)&As[nxt][a_sl0][a_gv] = ra0;
            *(float4*)&As[nxt][a_sl1][a_gv] = ra1;
            *(float4*)&Bs[nxt][b_sl][b_dv]  = rbv;
            __syncthreads();
        }
    }

    // Epilogue: out[b, d, g]
    float* ob = out + (size_t)b * HD * GPTS;
#pragma unroll
    for (int j = 0; j < 4; j++) {
        const int d = d0 + ty * 4 + j;
        float* orow = ob + (size_t)d * GPTS + g0;
        float4 lo = make_float4(acc[0][j], acc[1][j], acc[2][j], acc[3][j]);
        float4 hi = make_float4(acc[4][j], acc[5][j], acc[6][j], acc[7][j]);
        *(float4*)(orow + tx * 4)      = lo;
        *(float4*)(orow + 64 + tx * 4) = hi;
    }
}

// ---------------------------------------------------------------------------
// kernel_launch
// Inputs: station_features, station_coords, mask, W1, b1, W2, b2
// ---------------------------------------------------------------------------
extern "C" void kernel_launch(void* const* d_in, const int* in_sizes, int n_in,
                              void* d_out, int out_size)
{
    const float* features = (const float*)d_in[0];  // [2,1024,256]
    const float* coords   = (const float*)d_in[1];  // [2,1024,3]
    const float* mask     = (const float*)d_in[2];  // [2,1024]
    const float* W1       = (const float*)d_in[3];  // [3,32]
    const float* b1       = (const float*)d_in[4];  // [32]
    const float* W2       = (const float*)d_in[5];  // [32,1]
    const float* b2       = (const float*)d_in[6];  // [1]
    float* out            = (float*)d_out;          // [2,256,64,128]

    dim3 grid1(GPTS / 32, NB);
    weights_kernel<<<grid1, 256>>>(coords, mask, W1, b1, W2, b2);

    dim3 grid2(GPTS / TG, HD / TD, NB);
    grid_gemm_kernel<<<grid2, 256>>>(features, out);
}